// round 8
// baseline (speedup 1.0000x reference)
#include <cuda_runtime.h>
#include <cuda_fp16.h>
#include <cstdint>

#define NNODES 1000000
#define NGRAPHS 16384
#define NF 128          // node features (= K of GEMM)
#define GF 64           // global features
#define HID 64          // hidden (= N of GEMM)

// ---------------------------------------------------------------------------
// Scratch (device globals — no allocations allowed)
// ---------------------------------------------------------------------------
__device__ float g_U[NGRAPHS * HID];   // u @ W1u + b1
__device__ float g_E[NGRAPHS];         // sum exp(s) per graph (unnormalized)

// ---------------------------------------------------------------------------
// k_init: per-graph U projection + zero this graph's pooled row and g_E.
// One block of 64 threads per graph.
// ---------------------------------------------------------------------------
__global__ void k_init(const float* __restrict__ u, const float* __restrict__ W1,
                       const float* __restrict__ b1, float* __restrict__ pooled) {
    int g = blockIdx.x;
    int j = threadIdx.x;
    __shared__ float us[GF];
    us[j] = u[g * GF + j];
    ((float2*)(pooled + (size_t)g * NF))[j] = make_float2(0.f, 0.f);
    if (j == 0) g_E[g] = 0.f;
    __syncthreads();
    float acc = b1[j];
#pragma unroll 8
    for (int k = 0; k < GF; k++)
        acc = fmaf(us[k], W1[(NF + k) * HID + j], acc);
    g_U[g * HID + j] = acc;
}

// ---------------------------------------------------------------------------
// fp16 helpers
// ---------------------------------------------------------------------------
__device__ __forceinline__ uint32_t h2pack(float f0, float f1) {
    __half2 h = __floats2half2_rn(f0, f1);     // low = f0 (lower-k element)
    return *reinterpret_cast<uint32_t*>(&h);
}

__device__ __forceinline__ void mma16816h(float c[4], const uint32_t a[4],
                                          uint32_t b0, uint32_t b1) {
    asm volatile(
        "mma.sync.aligned.m16n8k16.row.col.f32.f16.f16.f32 "
        "{%0,%1,%2,%3}, {%4,%5,%6,%7}, {%8,%9}, {%0,%1,%2,%3};"
        : "+f"(c[0]), "+f"(c[1]), "+f"(c[2]), "+f"(c[3])
        : "r"(a[0]), "r"(a[1]), "r"(a[2]), "r"(a[3]), "r"(b0), "r"(b1));
}

// ---------------------------------------------------------------------------
// Fused tensor-core MLP + attention pool.
//   h = xh @ (wh + wl)  — fp16 2-term (proven rel_err ~1.1e-4).
// NEW: x fragments (already fp16) are staged into a warp-private smem tile
// during the mainloop; phase-2 pooling reads smem, NOT global -> removes the
// 512MB x re-read through L2. Warp-local everything; no block barriers.
// ---------------------------------------------------------------------------
struct SmemMMA {
    uint2 Bh[64 * 32];      // [kk*8+nt][lane] hi fragments   16KB
    uint2 Bl[64 * 32];      // lo residual                    16KB
    float w2[HID];
    float b2v;
    uint2 xt[4][32 * 33];   // per-warp fp16 x tile [row][cp], stride 33 (pad)
};

__global__ __launch_bounds__(128, 3)
void k_mlp_fused(const float* __restrict__ x, const float* __restrict__ W1,
                 const float* __restrict__ W2, const float* __restrict__ b2,
                 const int* __restrict__ batch, float* __restrict__ pooled,
                 float* __restrict__ attn, int n, int ntiles) {
    extern __shared__ unsigned char smraw[];
    SmemMMA& sm = *reinterpret_cast<SmemMMA*>(smraw);
    const int tid  = threadIdx.x;
    const int wid  = tid >> 5;
    const int lane = tid & 31;
    const int g8   = lane >> 2;          // groupID 0..7
    const int quad = lane & 3;           // 0..3
    uint2* xt_w = sm.xt[wid];

    // --- stage W1x^T hi/lo fp16 fragments, sigma-permuted ------------------
    for (int e = wid; e < 64; e += 4) {
        int nt = e & 7;
        int kk = e >> 3;
        int nn = nt * 8 + g8;
        int k0 = kk * 16 + quad * 4;
        float w0 = W1[(k0 + 0) * HID + nn];
        float w1 = W1[(k0 + 1) * HID + nn];
        float w2v = W1[(k0 + 2) * HID + nn];
        float w3 = W1[(k0 + 3) * HID + nn];
        __half h0 = __float2half_rn(w0), h1 = __float2half_rn(w1);
        __half h2 = __float2half_rn(w2v), h3 = __float2half_rn(w3);
        uint32_t bh0 = ((uint32_t)__half_as_ushort(h1) << 16) | __half_as_ushort(h0);
        uint32_t bh1 = ((uint32_t)__half_as_ushort(h3) << 16) | __half_as_ushort(h2);
        uint32_t bl0 = h2pack(w0 - __half2float(h0), w1 - __half2float(h1));
        uint32_t bl1 = h2pack(w2v - __half2float(h2), w3 - __half2float(h3));
        sm.Bh[e * 32 + lane] = make_uint2(bh0, bh1);
        sm.Bl[e * 32 + lane] = make_uint2(bl0, bl1);
    }
    if (tid < HID) sm.w2[tid] = W2[tid];
    if (tid == 0) sm.b2v = b2[0];
    __syncthreads();

    for (int t = blockIdx.x; t < ntiles; t += gridDim.x) {
        const int rowbase = t * 128 + wid * 32;

        int r0 = rowbase + g8;
        int cc0 = min(r0,      n - 1);
        int cc1 = min(r0 + 8,  n - 1);
        int cc2 = min(r0 + 16, n - 1);
        int cc3 = min(r0 + 24, n - 1);
        const float4* xp0 = (const float4*)(x + (size_t)cc0 * NF);
        const float4* xp1 = (const float4*)(x + (size_t)cc1 * NF);
        const float4* xp2 = (const float4*)(x + (size_t)cc2 * NF);
        const float4* xp3 = (const float4*)(x + (size_t)cc3 * NF);

        int gj[4];
        gj[0] = __ldg(batch + cc0);
        gj[1] = __ldg(batch + cc1);
        gj[2] = __ldg(batch + cc2);
        gj[3] = __ldg(batch + cc3);

        float c[2][8][4];
#pragma unroll
        for (int mt = 0; mt < 2; mt++)
#pragma unroll
            for (int nt = 0; nt < 8; nt++)
#pragma unroll
                for (int i = 0; i < 4; i++) c[mt][nt][i] = 0.f;

#pragma unroll 2
        for (int kk = 0; kk < 8; kk++) {
            float4 va = __ldg(xp0 + kk * 4 + quad);
            float4 vb = __ldg(xp1 + kk * 4 + quad);
            float4 vc = __ldg(xp2 + kk * 4 + quad);
            float4 vd = __ldg(xp3 + kk * 4 + quad);

            uint32_t a0[4], a1[4];
            a0[0] = h2pack(va.x, va.y);
            a0[1] = h2pack(vb.x, vb.y);
            a0[2] = h2pack(va.z, va.w);
            a0[3] = h2pack(vb.z, vb.w);
            a1[0] = h2pack(vc.x, vc.y);
            a1[1] = h2pack(vd.x, vd.y);
            a1[2] = h2pack(vc.z, vc.w);
            a1[3] = h2pack(vd.z, vd.w);

            // stage fp16 tile rows for phase-2 pooling (warp-private)
            int cp = kk * 4 + quad;     // uint2 col index: cols 4*cp..4*cp+3
            xt_w[(g8     ) * 33 + cp] = make_uint2(a0[0], a0[2]);
            xt_w[(g8 +  8) * 33 + cp] = make_uint2(a0[1], a0[3]);
            xt_w[(g8 + 16) * 33 + cp] = make_uint2(a1[0], a1[2]);
            xt_w[(g8 + 24) * 33 + cp] = make_uint2(a1[1], a1[3]);

#pragma unroll
            for (int nt = 0; nt < 8; nt++) {
                uint2 bh = sm.Bh[(kk * 8 + nt) * 32 + lane];
                uint2 bl = sm.Bl[(kk * 8 + nt) * 32 + lane];
                mma16816h(c[0][nt], a0, bh.x, bh.y);
                mma16816h(c[1][nt], a1, bh.x, bh.y);
                mma16816h(c[0][nt], a0, bl.x, bl.y);
                mma16816h(c[1][nt], a1, bl.x, bl.y);
            }
        }

        // --- epilogue: s = W2 . relu(c + U) + b2; write exp(s) to attn -----
        float ej[4];
#pragma unroll
        for (int mt = 0; mt < 2; mt++) {
            const float* Ua = g_U + gj[2 * mt] * HID;
            const float* Ub = g_U + gj[2 * mt + 1] * HID;
            float sa = 0.f, sb = 0.f;
#pragma unroll
            for (int nt = 0; nt < 8; nt++) {
                int n0 = nt * 8 + quad * 2;
                float2 ua = *(const float2*)(Ua + n0);
                float2 ub = *(const float2*)(Ub + n0);
                float w0 = sm.w2[n0], w1 = sm.w2[n0 + 1];
                sa = fmaf(w0, fmaxf(c[mt][nt][0] + ua.x, 0.f), sa);
                sa = fmaf(w1, fmaxf(c[mt][nt][1] + ua.y, 0.f), sa);
                sb = fmaf(w0, fmaxf(c[mt][nt][2] + ub.x, 0.f), sb);
                sb = fmaf(w1, fmaxf(c[mt][nt][3] + ub.y, 0.f), sb);
            }
            sa += __shfl_xor_sync(0xFFFFFFFF, sa, 1);
            sa += __shfl_xor_sync(0xFFFFFFFF, sa, 2);
            sb += __shfl_xor_sync(0xFFFFFFFF, sb, 1);
            sb += __shfl_xor_sync(0xFFFFFFFF, sb, 2);
            float eva = __expf(sa + sm.b2v);
            float evb = __expf(sb + sm.b2v);
            int ra = rowbase + mt * 16 + g8, rb = ra + 8;
            ej[2 * mt]     = (ra < n) ? eva : 0.f;
            ej[2 * mt + 1] = (rb < n) ? evb : 0.f;
            if (quad == 0) {
                if (ra < n) attn[ra] = eva;     // unnormalized; k_final divides
                if (rb < n) attn[rb] = evb;
            }
        }

        // --- phase 2 (warp-local): pool from the fp16 smem tile ------------
        __syncwarp();
        {
            float4 acc = make_float4(0.f, 0.f, 0.f, 0.f);
            float acce = 0.f;
            int curg = __shfl_sync(0xFFFFFFFF, gj[0], 0);
#pragma unroll
            for (int r = 0; r < 32; r++) {
                int j   = r >> 3;
                int src = (r & 7) * 4;
                float e = __shfl_sync(0xFFFFFFFF, ej[j], src);
                int   g = __shfl_sync(0xFFFFFFFF, gj[j], src);
                if (g != curg) {
                    float* dst = pooled + (size_t)curg * NF + lane * 4;
                    atomicAdd(dst + 0, acc.x);
                    atomicAdd(dst + 1, acc.y);
                    atomicAdd(dst + 2, acc.z);
                    atomicAdd(dst + 3, acc.w);
                    if (lane == 0) atomicAdd(&g_E[curg], acce);
                    acc = make_float4(0.f, 0.f, 0.f, 0.f);
                    acce = 0.f;
                    curg = g;
                }
                uint2 xv2 = xt_w[r * 33 + lane];
                float2 f0 = __half22float2(*reinterpret_cast<__half2*>(&xv2.x));
                float2 f1 = __half22float2(*reinterpret_cast<__half2*>(&xv2.y));
                acc.x = fmaf(f0.x, e, acc.x);
                acc.y = fmaf(f0.y, e, acc.y);
                acc.z = fmaf(f1.x, e, acc.z);
                acc.w = fmaf(f1.y, e, acc.w);
                acce += e;
            }
            float* dst = pooled + (size_t)curg * NF + lane * 4;
            atomicAdd(dst + 0, acc.x);
            atomicAdd(dst + 1, acc.y);
            atomicAdd(dst + 2, acc.z);
            atomicAdd(dst + 3, acc.w);
            if (lane == 0) atomicAdd(&g_E[curg], acce);
        }
        __syncwarp();   // xt WAR: next tile's STS vs this phase-2 LDS
    }
}

// ---------------------------------------------------------------------------
// k_final: pooled[i] /= E ; attn[j] /= E[batch[j]]
// ---------------------------------------------------------------------------
__global__ void k_final(const int* __restrict__ batch, float* __restrict__ attn,
                        float* __restrict__ pooled, int n) {
    int i = blockIdx.x * 256 + threadIdx.x;
    const int total = NGRAPHS * NF;
    if (i < total) {
        float E = g_E[i >> 7];
        pooled[i] = (E > 0.f) ? pooled[i] / E : 0.f;
    } else {
        int j = i - total;
        if (j < n) attn[j] /= g_E[__ldg(batch + j)];
    }
}

// ---------------------------------------------------------------------------
extern "C" void kernel_launch(void* const* d_in, const int* in_sizes, int n_in,
                              void* d_out, int out_size) {
    const float* x     = (const float*)d_in[0];
    const float* u     = (const float*)d_in[1];
    const int*   batch = (const int*)  d_in[2];
    const float* W1    = (const float*)d_in[3];
    const float* b1    = (const float*)d_in[4];
    const float* W2    = (const float*)d_in[5];
    const float* b2    = (const float*)d_in[6];

    float* pooled = (float*)d_out;                     // [16384, 128]
    float* attn   = (float*)d_out + NGRAPHS * NF;      // [1e6]

    int n = in_sizes[2];
    int ntiles = (n + 127) / 128;
    const int smem_bytes = (int)sizeof(SmemMMA);

    cudaFuncSetAttribute(k_mlp_fused, cudaFuncAttributeMaxDynamicSharedMemorySize,
                         smem_bytes);

    k_init<<<NGRAPHS, GF>>>(u, W1, b1, pooled);
    k_mlp_fused<<<444, 128, smem_bytes>>>(x, W1, W2, b2, batch, pooled, attn,
                                          n, ntiles);
    k_final<<<(NGRAPHS * NF + n + 255) / 256, 256>>>(batch, attn, pooled, n);
}

// round 9
// speedup vs baseline: 1.1257x; 1.1257x over previous
#include <cuda_runtime.h>
#include <cuda_fp16.h>
#include <cstdint>

#define NNODES 1000000
#define NGRAPHS 16384
#define NF 128          // node features (= K of GEMM)
#define GF 64           // global features
#define HID 64          // hidden (= N of GEMM)

// ---------------------------------------------------------------------------
// Scratch (device globals — no allocations allowed)
// ---------------------------------------------------------------------------
__device__ float g_U[NGRAPHS * HID];   // u @ W1u + b1
__device__ float g_E[NGRAPHS];         // sum exp(s) per graph (unnormalized)

// ---------------------------------------------------------------------------
// k_init: U projection + zero pooled rows + zero g_E. 4 graphs / 256-thr block.
// ---------------------------------------------------------------------------
__global__ __launch_bounds__(256)
void k_init(const float* __restrict__ u, const float* __restrict__ W1,
            const float* __restrict__ b1, float* __restrict__ pooled) {
    __shared__ float us[4][GF];
    int sub = threadIdx.x >> 6;           // 0..3  graph-group
    int j   = threadIdx.x & 63;           // 0..63
    int g   = blockIdx.x * 4 + sub;
    us[sub][j] = u[g * GF + j];
    ((float2*)(pooled + (size_t)g * NF))[j] = make_float2(0.f, 0.f);
    if (j == 0) g_E[g] = 0.f;
    __syncthreads();
    float acc = b1[j];
#pragma unroll 8
    for (int k = 0; k < GF; k++)
        acc = fmaf(us[sub][k], W1[(NF + k) * HID + j], acc);
    g_U[g * HID + j] = acc;
}

// ---------------------------------------------------------------------------
// fp16 helpers + hinted loads
// ---------------------------------------------------------------------------
__device__ __forceinline__ uint32_t h2pack(float f0, float f1) {
    __half2 h = __floats2half2_rn(f0, f1);     // low = f0 (lower-k element)
    return *reinterpret_cast<uint32_t*>(&h);
}

// phase-1 x load: keep resident in L1 for the phase-2 re-read
__device__ __forceinline__ float4 ldg_keep(const float4* p) {
    float4 v;
    asm("ld.global.nc.L1::evict_last.v4.f32 {%0,%1,%2,%3}, [%4];"
        : "=f"(v.x), "=f"(v.y), "=f"(v.z), "=f"(v.w) : "l"(p));
    return v;
}
// phase-2 x load: consume and discard
__device__ __forceinline__ float4 ldg_stream(const float4* p) {
    float4 v;
    asm("ld.global.nc.L1::evict_first.v4.f32 {%0,%1,%2,%3}, [%4];"
        : "=f"(v.x), "=f"(v.y), "=f"(v.z), "=f"(v.w) : "l"(p));
    return v;
}

__device__ __forceinline__ void mma16816h(float c[4], const uint32_t a[4],
                                          uint32_t b0, uint32_t b1) {
    asm volatile(
        "mma.sync.aligned.m16n8k16.row.col.f32.f16.f16.f32 "
        "{%0,%1,%2,%3}, {%4,%5,%6,%7}, {%8,%9}, {%0,%1,%2,%3};"
        : "+f"(c[0]), "+f"(c[1]), "+f"(c[2]), "+f"(c[3])
        : "r"(a[0]), "r"(a[1]), "r"(a[2]), "r"(a[3]), "r"(b0), "r"(b1));
}

// ---------------------------------------------------------------------------
// Fused tensor-core MLP + attention pool (R7 structure, proven 187us).
//   h = xh @ (wh + wl)  — fp16 2-term (rel_err ~1.1e-4).
// B hi/lo fragments interleaved in one uint4 -> LDS.128.
// Phase-1 loads evict_last; phase-2 re-reads evict_first (L1-resident).
// Warp-local pooling via shfl; no block barriers in the loop.
// ---------------------------------------------------------------------------
struct SmemMMA {
    uint4 B[64 * 32];       // [kk*8+nt][lane] = {bh0, bh1, bl0, bl1}  32KB
    float w2[HID];
    float b2v;
};

__global__ __launch_bounds__(128, 3)
void k_mlp_fused(const float* __restrict__ x, const float* __restrict__ W1,
                 const float* __restrict__ W2, const float* __restrict__ b2,
                 const int* __restrict__ batch, float* __restrict__ pooled,
                 float* __restrict__ attn, int n, int ntiles) {
    __shared__ SmemMMA sm;
    const int tid  = threadIdx.x;
    const int wid  = tid >> 5;
    const int lane = tid & 31;
    const int g8   = lane >> 2;          // groupID 0..7
    const int quad = lane & 3;           // 0..3

    // --- stage W1x^T hi/lo fp16 fragments, sigma-permuted ------------------
    // e = kk*8+nt ; bh0: k0..k0+1, bh1: k0+2..k0+3 ; k0 = kk*16 + quad*4 ;
    // n = nt*8 + g8.
    for (int e = wid; e < 64; e += 4) {
        int nt = e & 7;
        int kk = e >> 3;
        int nn = nt * 8 + g8;
        int k0 = kk * 16 + quad * 4;
        float w0 = W1[(k0 + 0) * HID + nn];
        float w1 = W1[(k0 + 1) * HID + nn];
        float w2v = W1[(k0 + 2) * HID + nn];
        float w3 = W1[(k0 + 3) * HID + nn];
        __half h0 = __float2half_rn(w0), h1 = __float2half_rn(w1);
        __half h2 = __float2half_rn(w2v), h3 = __float2half_rn(w3);
        uint32_t bh0 = ((uint32_t)__half_as_ushort(h1) << 16) | __half_as_ushort(h0);
        uint32_t bh1 = ((uint32_t)__half_as_ushort(h3) << 16) | __half_as_ushort(h2);
        uint32_t bl0 = h2pack(w0 - __half2float(h0), w1 - __half2float(h1));
        uint32_t bl1 = h2pack(w2v - __half2float(h2), w3 - __half2float(h3));
        sm.B[e * 32 + lane] = make_uint4(bh0, bh1, bl0, bl1);
    }
    if (tid < HID) sm.w2[tid] = W2[tid];
    if (tid == 0) sm.b2v = b2[0];
    __syncthreads();

    for (int t = blockIdx.x; t < ntiles; t += gridDim.x) {
        const int rowbase = t * 128 + wid * 32;

        int r0 = rowbase + g8;
        int cc0 = min(r0,      n - 1);
        int cc1 = min(r0 + 8,  n - 1);
        int cc2 = min(r0 + 16, n - 1);
        int cc3 = min(r0 + 24, n - 1);
        const float4* xp0 = (const float4*)(x + (size_t)cc0 * NF);
        const float4* xp1 = (const float4*)(x + (size_t)cc1 * NF);
        const float4* xp2 = (const float4*)(x + (size_t)cc2 * NF);
        const float4* xp3 = (const float4*)(x + (size_t)cc3 * NF);

        int gj[4];
        gj[0] = __ldg(batch + cc0);
        gj[1] = __ldg(batch + cc1);
        gj[2] = __ldg(batch + cc2);
        gj[3] = __ldg(batch + cc3);

        float c[2][8][4];
#pragma unroll
        for (int mt = 0; mt < 2; mt++)
#pragma unroll
            for (int nt = 0; nt < 8; nt++)
#pragma unroll
                for (int i = 0; i < 4; i++) c[mt][nt][i] = 0.f;

#pragma unroll 2
        for (int kk = 0; kk < 8; kk++) {
            float4 va = ldg_keep(xp0 + kk * 4 + quad);
            float4 vb = ldg_keep(xp1 + kk * 4 + quad);
            float4 vc = ldg_keep(xp2 + kk * 4 + quad);
            float4 vd = ldg_keep(xp3 + kk * 4 + quad);

            uint32_t a0[4], a1[4];
            a0[0] = h2pack(va.x, va.y);
            a0[1] = h2pack(vb.x, vb.y);
            a0[2] = h2pack(va.z, va.w);
            a0[3] = h2pack(vb.z, vb.w);
            a1[0] = h2pack(vc.x, vc.y);
            a1[1] = h2pack(vd.x, vd.y);
            a1[2] = h2pack(vc.z, vc.w);
            a1[3] = h2pack(vd.z, vd.w);

#pragma unroll
            for (int nt = 0; nt < 8; nt++) {
                uint4 b = sm.B[(kk * 8 + nt) * 32 + lane];
                mma16816h(c[0][nt], a0, b.x, b.y);
                mma16816h(c[1][nt], a1, b.x, b.y);
                mma16816h(c[0][nt], a0, b.z, b.w);
                mma16816h(c[1][nt], a1, b.z, b.w);
            }
        }

        // --- epilogue: s = W2 . relu(c + U) + b2; write exp(s) to attn -----
        float ej[4];
#pragma unroll
        for (int mt = 0; mt < 2; mt++) {
            const float* Ua = g_U + gj[2 * mt] * HID;
            const float* Ub = g_U + gj[2 * mt + 1] * HID;
            float sa = 0.f, sb = 0.f;
#pragma unroll
            for (int nt = 0; nt < 8; nt++) {
                int n0 = nt * 8 + quad * 2;
                float2 ua = *(const float2*)(Ua + n0);
                float2 ub = *(const float2*)(Ub + n0);
                float w0 = sm.w2[n0], w1 = sm.w2[n0 + 1];
                sa = fmaf(w0, fmaxf(c[mt][nt][0] + ua.x, 0.f), sa);
                sa = fmaf(w1, fmaxf(c[mt][nt][1] + ua.y, 0.f), sa);
                sb = fmaf(w0, fmaxf(c[mt][nt][2] + ub.x, 0.f), sb);
                sb = fmaf(w1, fmaxf(c[mt][nt][3] + ub.y, 0.f), sb);
            }
            sa += __shfl_xor_sync(0xFFFFFFFF, sa, 1);
            sa += __shfl_xor_sync(0xFFFFFFFF, sa, 2);
            sb += __shfl_xor_sync(0xFFFFFFFF, sb, 1);
            sb += __shfl_xor_sync(0xFFFFFFFF, sb, 2);
            float eva = __expf(sa + sm.b2v);
            float evb = __expf(sb + sm.b2v);
            int ra = rowbase + mt * 16 + g8, rb = ra + 8;
            ej[2 * mt]     = (ra < n) ? eva : 0.f;
            ej[2 * mt + 1] = (rb < n) ? evb : 0.f;
            if (quad == 0) {
                if (ra < n) attn[ra] = eva;     // unnormalized; k_final divides
                if (rb < n) attn[rb] = evb;
            }
        }

        // --- phase 2 (warp-local): pool this warp's 32 rows (L1-resident) ---
        {
            float4 acc = make_float4(0.f, 0.f, 0.f, 0.f);
            float acce = 0.f;
            int curg = __shfl_sync(0xFFFFFFFF, gj[0], 0);
#pragma unroll
            for (int r = 0; r < 32; r++) {
                int j   = r >> 3;
                int src = (r & 7) * 4;
                float e = __shfl_sync(0xFFFFFFFF, ej[j], src);
                int   g = __shfl_sync(0xFFFFFFFF, gj[j], src);
                if (g != curg) {
                    float* dst = pooled + (size_t)curg * NF + lane * 4;
                    atomicAdd(dst + 0, acc.x);
                    atomicAdd(dst + 1, acc.y);
                    atomicAdd(dst + 2, acc.z);
                    atomicAdd(dst + 3, acc.w);
                    if (lane == 0) atomicAdd(&g_E[curg], acce);
                    acc = make_float4(0.f, 0.f, 0.f, 0.f);
                    acce = 0.f;
                    curg = g;
                }
                int rr = min(rowbase + r, n - 1);
                float4 xv = ldg_stream((const float4*)(x + (size_t)rr * NF) + lane);
                acc.x = fmaf(xv.x, e, acc.x);
                acc.y = fmaf(xv.y, e, acc.y);
                acc.z = fmaf(xv.z, e, acc.z);
                acc.w = fmaf(xv.w, e, acc.w);
                acce += e;
            }
            float* dst = pooled + (size_t)curg * NF + lane * 4;
            atomicAdd(dst + 0, acc.x);
            atomicAdd(dst + 1, acc.y);
            atomicAdd(dst + 2, acc.z);
            atomicAdd(dst + 3, acc.w);
            if (lane == 0) atomicAdd(&g_E[curg], acce);
        }
    }
}

// ---------------------------------------------------------------------------
// k_final: pooled[i] /= E ; attn[j] /= E[batch[j]]
// ---------------------------------------------------------------------------
__global__ void k_final(const int* __restrict__ batch, float* __restrict__ attn,
                        float* __restrict__ pooled, int n) {
    int i = blockIdx.x * 256 + threadIdx.x;
    const int total = NGRAPHS * NF;
    if (i < total) {
        float E = g_E[i >> 7];
        pooled[i] = (E > 0.f) ? pooled[i] / E : 0.f;
    } else {
        int j = i - total;
        if (j < n) attn[j] /= g_E[__ldg(batch + j)];
    }
}

// ---------------------------------------------------------------------------
extern "C" void kernel_launch(void* const* d_in, const int* in_sizes, int n_in,
                              void* d_out, int out_size) {
    const float* x     = (const float*)d_in[0];
    const float* u     = (const float*)d_in[1];
    const int*   batch = (const int*)  d_in[2];
    const float* W1    = (const float*)d_in[3];
    const float* b1    = (const float*)d_in[4];
    const float* W2    = (const float*)d_in[5];
    const float* b2    = (const float*)d_in[6];

    float* pooled = (float*)d_out;                     // [16384, 128]
    float* attn   = (float*)d_out + NGRAPHS * NF;      // [1e6]

    int n = in_sizes[2];
    int ntiles = (n + 127) / 128;

    k_init<<<NGRAPHS / 4, 256>>>(u, W1, b1, pooled);
    k_mlp_fused<<<444, 128>>>(x, W1, W2, b2, batch, pooled, attn, n, ntiles);
    k_final<<<(NGRAPHS * NF + n + 255) / 256, 256>>>(batch, attn, pooled, n);
}

// round 10
// speedup vs baseline: 1.1815x; 1.0496x over previous
#include <cuda_runtime.h>
#include <cuda_fp16.h>
#include <cstdint>

#define NNODES 1000000
#define NGRAPHS 16384
#define NF 128          // node features (= K of GEMM)
#define GF 64           // global features
#define HID 64          // hidden (= N of GEMM)

// ---------------------------------------------------------------------------
// Scratch (device globals — no allocations allowed)
// ---------------------------------------------------------------------------
__device__ float g_U[NGRAPHS * HID];   // u @ W1u + b1
__device__ float g_E[NGRAPHS];         // sum exp(s) per graph (unnormalized)

// ---------------------------------------------------------------------------
// k_init: U projection + zero pooled rows + zero g_E.
// Persistent: 592 blocks x 256 thr, 4 graphs per block-iteration.
// ---------------------------------------------------------------------------
__global__ __launch_bounds__(256)
void k_init(const float* __restrict__ u, const float* __restrict__ W1,
            const float* __restrict__ b1, float* __restrict__ pooled) {
    __shared__ float us[4][GF];
    int sub = threadIdx.x >> 6;           // 0..3  graph-group
    int j   = threadIdx.x & 63;           // 0..63
    for (int g = blockIdx.x * 4 + sub; g < NGRAPHS; g += gridDim.x * 4) {
        us[sub][j] = __ldg(u + g * GF + j);
        ((float2*)(pooled + (size_t)g * NF))[j] = make_float2(0.f, 0.f);
        if (j == 0) g_E[g] = 0.f;
        __syncthreads();
        float acc = __ldg(b1 + j);
#pragma unroll 8
        for (int k = 0; k < GF; k++)
            acc = fmaf(us[sub][k], __ldg(W1 + (NF + k) * HID + j), acc);
        g_U[g * HID + j] = acc;
        __syncthreads();
    }
}

// ---------------------------------------------------------------------------
// fp16 helpers
// ---------------------------------------------------------------------------
__device__ __forceinline__ uint32_t h2pack(float f0, float f1) {
    __half2 h = __floats2half2_rn(f0, f1);     // low = f0 (lower-k element)
    return *reinterpret_cast<uint32_t*>(&h);
}

__device__ __forceinline__ void mma16816h(float c[4], const uint32_t a[4],
                                          uint32_t b0, uint32_t b1) {
    asm volatile(
        "mma.sync.aligned.m16n8k16.row.col.f32.f16.f16.f32 "
        "{%0,%1,%2,%3}, {%4,%5,%6,%7}, {%8,%9}, {%0,%1,%2,%3};"
        : "+f"(c[0]), "+f"(c[1]), "+f"(c[2]), "+f"(c[3])
        : "r"(a[0]), "r"(a[1]), "r"(a[2]), "r"(a[3]), "r"(b0), "r"(b1));
}

// ---------------------------------------------------------------------------
// Fused tensor-core MLP + attention pool — fp16 SINGLE-term scheme.
//   h = fp16(x) @ fp16(W1x)   (error ~1.6e-4, 6x under the 1e-3 gate)
// Halves HMMA count vs R7's 2-term — the measured binding pipe.
// k-axis sigma-permuted; warp-local phase-2 pooling; no block barriers.
// ---------------------------------------------------------------------------
struct SmemMMA {
    uint2 B[64 * 32];       // [kk*8+nt][lane] = {b0, b1}  16KB
    float w2[HID];
    float b2v;
};

__global__ __launch_bounds__(128, 3)
void k_mlp_fused(const float* __restrict__ x, const float* __restrict__ W1,
                 const float* __restrict__ W2, const float* __restrict__ b2,
                 const int* __restrict__ batch, float* __restrict__ pooled,
                 float* __restrict__ attn, int n, int ntiles) {
    __shared__ SmemMMA sm;
    const int tid  = threadIdx.x;
    const int wid  = tid >> 5;
    const int lane = tid & 31;
    const int g8   = lane >> 2;          // groupID 0..7
    const int quad = lane & 3;           // 0..3

    // --- stage W1x^T fp16 fragments, sigma-permuted ------------------------
    // e = kk*8+nt ; b0: k0..k0+1, b1: k0+2..k0+3 ; k0 = kk*16 + quad*4 ;
    // n = nt*8 + g8.
    for (int e = wid; e < 64; e += 4) {
        int nt = e & 7;
        int kk = e >> 3;
        int nn = nt * 8 + g8;
        int k0 = kk * 16 + quad * 4;
        float w0 = W1[(k0 + 0) * HID + nn];
        float w1 = W1[(k0 + 1) * HID + nn];
        float w2v = W1[(k0 + 2) * HID + nn];
        float w3 = W1[(k0 + 3) * HID + nn];
        sm.B[e * 32 + lane] = make_uint2(h2pack(w0, w1), h2pack(w2v, w3));
    }
    if (tid < HID) sm.w2[tid] = W2[tid];
    if (tid == 0) sm.b2v = b2[0];
    __syncthreads();

    for (int t = blockIdx.x; t < ntiles; t += gridDim.x) {
        const int rowbase = t * 128 + wid * 32;

        int r0 = rowbase + g8;
        int cc0 = min(r0,      n - 1);
        int cc1 = min(r0 + 8,  n - 1);
        int cc2 = min(r0 + 16, n - 1);
        int cc3 = min(r0 + 24, n - 1);
        const float4* xp0 = (const float4*)(x + (size_t)cc0 * NF);
        const float4* xp1 = (const float4*)(x + (size_t)cc1 * NF);
        const float4* xp2 = (const float4*)(x + (size_t)cc2 * NF);
        const float4* xp3 = (const float4*)(x + (size_t)cc3 * NF);

        int gj[4];
        gj[0] = __ldg(batch + cc0);
        gj[1] = __ldg(batch + cc1);
        gj[2] = __ldg(batch + cc2);
        gj[3] = __ldg(batch + cc3);

        float c[2][8][4];
#pragma unroll
        for (int mt = 0; mt < 2; mt++)
#pragma unroll
            for (int nt = 0; nt < 8; nt++)
#pragma unroll
                for (int i = 0; i < 4; i++) c[mt][nt][i] = 0.f;

#pragma unroll 2
        for (int kk = 0; kk < 8; kk++) {
            float4 va = __ldg(xp0 + kk * 4 + quad);
            float4 vb = __ldg(xp1 + kk * 4 + quad);
            float4 vc = __ldg(xp2 + kk * 4 + quad);
            float4 vd = __ldg(xp3 + kk * 4 + quad);

            uint32_t a0[4], a1[4];
            a0[0] = h2pack(va.x, va.y);
            a0[1] = h2pack(vb.x, vb.y);
            a0[2] = h2pack(va.z, va.w);
            a0[3] = h2pack(vb.z, vb.w);
            a1[0] = h2pack(vc.x, vc.y);
            a1[1] = h2pack(vd.x, vd.y);
            a1[2] = h2pack(vc.z, vc.w);
            a1[3] = h2pack(vd.z, vd.w);

#pragma unroll
            for (int nt = 0; nt < 8; nt++) {
                uint2 b = sm.B[(kk * 8 + nt) * 32 + lane];
                mma16816h(c[0][nt], a0, b.x, b.y);
                mma16816h(c[1][nt], a1, b.x, b.y);
            }
        }

        // --- epilogue: s = W2 . relu(c + U) + b2; write exp(s) to attn -----
        float ej[4];
#pragma unroll
        for (int mt = 0; mt < 2; mt++) {
            const float* Ua = g_U + gj[2 * mt] * HID;
            const float* Ub = g_U + gj[2 * mt + 1] * HID;
            float sa = 0.f, sb = 0.f;
#pragma unroll
            for (int nt = 0; nt < 8; nt++) {
                int n0 = nt * 8 + quad * 2;
                float2 ua = *(const float2*)(Ua + n0);
                float2 ub = *(const float2*)(Ub + n0);
                float w0 = sm.w2[n0], w1 = sm.w2[n0 + 1];
                sa = fmaf(w0, fmaxf(c[mt][nt][0] + ua.x, 0.f), sa);
                sa = fmaf(w1, fmaxf(c[mt][nt][1] + ua.y, 0.f), sa);
                sb = fmaf(w0, fmaxf(c[mt][nt][2] + ub.x, 0.f), sb);
                sb = fmaf(w1, fmaxf(c[mt][nt][3] + ub.y, 0.f), sb);
            }
            sa += __shfl_xor_sync(0xFFFFFFFF, sa, 1);
            sa += __shfl_xor_sync(0xFFFFFFFF, sa, 2);
            sb += __shfl_xor_sync(0xFFFFFFFF, sb, 1);
            sb += __shfl_xor_sync(0xFFFFFFFF, sb, 2);
            float eva = __expf(sa + sm.b2v);
            float evb = __expf(sb + sm.b2v);
            int ra = rowbase + mt * 16 + g8, rb = ra + 8;
            ej[2 * mt]     = (ra < n) ? eva : 0.f;
            ej[2 * mt + 1] = (rb < n) ? evb : 0.f;
            if (quad == 0) {
                if (ra < n) attn[ra] = eva;     // unnormalized; k_final divides
                if (rb < n) attn[rb] = evb;
            }
        }

        // --- phase 2 (warp-local): pool this warp's 32 rows ----------------
        {
            float4 acc = make_float4(0.f, 0.f, 0.f, 0.f);
            float acce = 0.f;
            int curg = __shfl_sync(0xFFFFFFFF, gj[0], 0);
#pragma unroll
            for (int r = 0; r < 32; r++) {
                int j   = r >> 3;
                int src = (r & 7) * 4;
                float e = __shfl_sync(0xFFFFFFFF, ej[j], src);
                int   g = __shfl_sync(0xFFFFFFFF, gj[j], src);
                if (g != curg) {
                    float* dst = pooled + (size_t)curg * NF + lane * 4;
                    atomicAdd(dst + 0, acc.x);
                    atomicAdd(dst + 1, acc.y);
                    atomicAdd(dst + 2, acc.z);
                    atomicAdd(dst + 3, acc.w);
                    if (lane == 0) atomicAdd(&g_E[curg], acce);
                    acc = make_float4(0.f, 0.f, 0.f, 0.f);
                    acce = 0.f;
                    curg = g;
                }
                int rr = min(rowbase + r, n - 1);
                float4 xv = __ldg((const float4*)(x + (size_t)rr * NF) + lane);
                acc.x = fmaf(xv.x, e, acc.x);
                acc.y = fmaf(xv.y, e, acc.y);
                acc.z = fmaf(xv.z, e, acc.z);
                acc.w = fmaf(xv.w, e, acc.w);
                acce += e;
            }
            float* dst = pooled + (size_t)curg * NF + lane * 4;
            atomicAdd(dst + 0, acc.x);
            atomicAdd(dst + 1, acc.y);
            atomicAdd(dst + 2, acc.z);
            atomicAdd(dst + 3, acc.w);
            if (lane == 0) atomicAdd(&g_E[curg], acce);
        }
    }
}

// ---------------------------------------------------------------------------
// k_final: pooled[i] /= E ; attn[j] /= E[batch[j]]
// ---------------------------------------------------------------------------
__global__ void k_final(const int* __restrict__ batch, float* __restrict__ attn,
                        float* __restrict__ pooled, int n) {
    int i = blockIdx.x * 256 + threadIdx.x;
    const int total = NGRAPHS * NF;
    if (i < total) {
        float E = g_E[i >> 7];
        pooled[i] = (E > 0.f) ? pooled[i] / E : 0.f;
    } else {
        int j = i - total;
        if (j < n) attn[j] /= g_E[__ldg(batch + j)];
    }
}

// ---------------------------------------------------------------------------
extern "C" void kernel_launch(void* const* d_in, const int* in_sizes, int n_in,
                              void* d_out, int out_size) {
    const float* x     = (const float*)d_in[0];
    const float* u     = (const float*)d_in[1];
    const int*   batch = (const int*)  d_in[2];
    const float* W1    = (const float*)d_in[3];
    const float* b1    = (const float*)d_in[4];
    const float* W2    = (const float*)d_in[5];
    const float* b2    = (const float*)d_in[6];

    float* pooled = (float*)d_out;                     // [16384, 128]
    float* attn   = (float*)d_out + NGRAPHS * NF;      // [1e6]

    int n = in_sizes[2];
    int ntiles = (n + 127) / 128;

    k_init<<<592, 256>>>(u, W1, b1, pooled);
    k_mlp_fused<<<444, 128>>>(x, W1, W2, b2, batch, pooled, attn, n, ntiles);
    k_final<<<(NGRAPHS * NF + n + 255) / 256, 256>>>(batch, attn, pooled, n);
}

// round 11
// speedup vs baseline: 1.2917x; 1.0933x over previous
#include <cuda_runtime.h>
#include <cuda_fp16.h>
#include <cstdint>

#define NNODES 1000000
#define NGRAPHS 16384
#define NF 128          // node features (= K of GEMM)
#define GF 64           // global features
#define HID 64          // hidden (= N of GEMM)

// ---------------------------------------------------------------------------
// Scratch (device globals — no allocations allowed)
// ---------------------------------------------------------------------------
__device__ float g_U[NGRAPHS * HID];   // u @ W1u + b1
__device__ float g_E[NGRAPHS];         // sum exp(s) per graph (unnormalized)

// ---------------------------------------------------------------------------
// k_init: U projection + zero pooled rows + zero g_E.
// Persistent 296 x 256thr; W1u column register-cached (loaded ONCE).
// ---------------------------------------------------------------------------
__global__ __launch_bounds__(256)
void k_init(const float* __restrict__ u, const float* __restrict__ W1,
            const float* __restrict__ b1, float* __restrict__ pooled) {
    __shared__ float us[4][GF];
    int sub = threadIdx.x >> 6;           // 0..3  graph-group
    int j   = threadIdx.x & 63;           // 0..63
    float wcol[GF];
#pragma unroll
    for (int k = 0; k < GF; k++) wcol[k] = __ldg(W1 + (NF + k) * HID + j);
    float b1j = __ldg(b1 + j);

    for (int g = blockIdx.x * 4 + sub; g < NGRAPHS; g += gridDim.x * 4) {
        us[sub][j] = __ldg(u + g * GF + j);
        ((float2*)(pooled + (size_t)g * NF))[j] = make_float2(0.f, 0.f);
        if (j == 0) g_E[g] = 0.f;
        __syncthreads();
        float acc = b1j;
#pragma unroll
        for (int k = 0; k < GF; k++)
            acc = fmaf(us[sub][k], wcol[k], acc);
        g_U[g * HID + j] = acc;
        __syncthreads();
    }
}

// ---------------------------------------------------------------------------
// fp16 helpers
// ---------------------------------------------------------------------------
__device__ __forceinline__ uint32_t h2pack(float f0, float f1) {
    __half2 h = __floats2half2_rn(f0, f1);     // low = f0 (lower-k element)
    return *reinterpret_cast<uint32_t*>(&h);
}

__device__ __forceinline__ void mma16816h(float c[4], const uint32_t a[4],
                                          uint32_t b0, uint32_t b1) {
    asm volatile(
        "mma.sync.aligned.m16n8k16.row.col.f32.f16.f16.f32 "
        "{%0,%1,%2,%3}, {%4,%5,%6,%7}, {%8,%9}, {%0,%1,%2,%3};"
        : "+f"(c[0]), "+f"(c[1]), "+f"(c[2]), "+f"(c[3])
        : "r"(a[0]), "r"(a[1]), "r"(a[2]), "r"(a[3]), "r"(b0), "r"(b1));
}

// ---------------------------------------------------------------------------
// Fused tensor-core MLP + attention pool — fp16 single-term (rel_err 1.6e-4).
// R11: occupancy 4 CTAs/SM (4 warps/SMSP) + deeper kk unroll for DRAM-latency
// hiding — the measured residual after MMA-halving proved non-binding.
// ---------------------------------------------------------------------------
struct SmemMMA {
    uint2 B[64 * 32];       // [kk*8+nt][lane] = {b0, b1}  16KB
    float w2[HID];
    float b2v;
};

__global__ __launch_bounds__(128, 4)
void k_mlp_fused(const float* __restrict__ x, const float* __restrict__ W1,
                 const float* __restrict__ W2, const float* __restrict__ b2,
                 const int* __restrict__ batch, float* __restrict__ pooled,
                 float* __restrict__ attn, int n, int ntiles) {
    __shared__ SmemMMA sm;
    const int tid  = threadIdx.x;
    const int wid  = tid >> 5;
    const int lane = tid & 31;
    const int g8   = lane >> 2;          // groupID 0..7
    const int quad = lane & 3;           // 0..3

    // --- stage W1x^T fp16 fragments, sigma-permuted ------------------------
    for (int e = wid; e < 64; e += 4) {
        int nt = e & 7;
        int kk = e >> 3;
        int nn = nt * 8 + g8;
        int k0 = kk * 16 + quad * 4;
        float w0 = W1[(k0 + 0) * HID + nn];
        float w1 = W1[(k0 + 1) * HID + nn];
        float w2v = W1[(k0 + 2) * HID + nn];
        float w3 = W1[(k0 + 3) * HID + nn];
        sm.B[e * 32 + lane] = make_uint2(h2pack(w0, w1), h2pack(w2v, w3));
    }
    if (tid < HID) sm.w2[tid] = W2[tid];
    if (tid == 0) sm.b2v = b2[0];
    __syncthreads();

    for (int t = blockIdx.x; t < ntiles; t += gridDim.x) {
        const int rowbase = t * 128 + wid * 32;

        int r0 = rowbase + g8;
        int cc0 = min(r0,      n - 1);
        int cc1 = min(r0 + 8,  n - 1);
        int cc2 = min(r0 + 16, n - 1);
        int cc3 = min(r0 + 24, n - 1);
        const float4* xp0 = (const float4*)(x + (size_t)cc0 * NF);
        const float4* xp1 = (const float4*)(x + (size_t)cc1 * NF);
        const float4* xp2 = (const float4*)(x + (size_t)cc2 * NF);
        const float4* xp3 = (const float4*)(x + (size_t)cc3 * NF);

        int gj[4];
        gj[0] = __ldg(batch + cc0);
        gj[1] = __ldg(batch + cc1);
        gj[2] = __ldg(batch + cc2);
        gj[3] = __ldg(batch + cc3);

        float c[2][8][4];
#pragma unroll
        for (int mt = 0; mt < 2; mt++)
#pragma unroll
            for (int nt = 0; nt < 8; nt++)
#pragma unroll
                for (int i = 0; i < 4; i++) c[mt][nt][i] = 0.f;

#pragma unroll 4
        for (int kk = 0; kk < 8; kk++) {
            float4 va = __ldg(xp0 + kk * 4 + quad);
            float4 vb = __ldg(xp1 + kk * 4 + quad);
            float4 vc = __ldg(xp2 + kk * 4 + quad);
            float4 vd = __ldg(xp3 + kk * 4 + quad);

            uint32_t a0[4], a1[4];
            a0[0] = h2pack(va.x, va.y);
            a0[1] = h2pack(vb.x, vb.y);
            a0[2] = h2pack(va.z, va.w);
            a0[3] = h2pack(vb.z, vb.w);
            a1[0] = h2pack(vc.x, vc.y);
            a1[1] = h2pack(vd.x, vd.y);
            a1[2] = h2pack(vc.z, vc.w);
            a1[3] = h2pack(vd.z, vd.w);

#pragma unroll
            for (int nt = 0; nt < 8; nt++) {
                uint2 b = sm.B[(kk * 8 + nt) * 32 + lane];
                mma16816h(c[0][nt], a0, b.x, b.y);
                mma16816h(c[1][nt], a1, b.x, b.y);
            }
        }

        // --- epilogue: s = W2 . relu(c + U) + b2; write exp(s) to attn -----
        float ej[4];
#pragma unroll
        for (int mt = 0; mt < 2; mt++) {
            const float* Ua = g_U + gj[2 * mt] * HID;
            const float* Ub = g_U + gj[2 * mt + 1] * HID;
            float sa = 0.f, sb = 0.f;
#pragma unroll
            for (int nt = 0; nt < 8; nt++) {
                int n0 = nt * 8 + quad * 2;
                float2 ua = *(const float2*)(Ua + n0);
                float2 ub = *(const float2*)(Ub + n0);
                float w0 = sm.w2[n0], w1 = sm.w2[n0 + 1];
                sa = fmaf(w0, fmaxf(c[mt][nt][0] + ua.x, 0.f), sa);
                sa = fmaf(w1, fmaxf(c[mt][nt][1] + ua.y, 0.f), sa);
                sb = fmaf(w0, fmaxf(c[mt][nt][2] + ub.x, 0.f), sb);
                sb = fmaf(w1, fmaxf(c[mt][nt][3] + ub.y, 0.f), sb);
            }
            sa += __shfl_xor_sync(0xFFFFFFFF, sa, 1);
            sa += __shfl_xor_sync(0xFFFFFFFF, sa, 2);
            sb += __shfl_xor_sync(0xFFFFFFFF, sb, 1);
            sb += __shfl_xor_sync(0xFFFFFFFF, sb, 2);
            float eva = __expf(sa + sm.b2v);
            float evb = __expf(sb + sm.b2v);
            int ra = rowbase + mt * 16 + g8, rb = ra + 8;
            ej[2 * mt]     = (ra < n) ? eva : 0.f;
            ej[2 * mt + 1] = (rb < n) ? evb : 0.f;
            if (quad == 0) {
                if (ra < n) attn[ra] = eva;     // unnormalized; k_final divides
                if (rb < n) attn[rb] = evb;
            }
        }

        // --- phase 2 (warp-local): pool this warp's 32 rows ----------------
        {
            float4 acc = make_float4(0.f, 0.f, 0.f, 0.f);
            float acce = 0.f;
            int curg = __shfl_sync(0xFFFFFFFF, gj[0], 0);
#pragma unroll
            for (int r = 0; r < 32; r++) {
                int j   = r >> 3;
                int src = (r & 7) * 4;
                float e = __shfl_sync(0xFFFFFFFF, ej[j], src);
                int   g = __shfl_sync(0xFFFFFFFF, gj[j], src);
                if (g != curg) {
                    float* dst = pooled + (size_t)curg * NF + lane * 4;
                    atomicAdd(dst + 0, acc.x);
                    atomicAdd(dst + 1, acc.y);
                    atomicAdd(dst + 2, acc.z);
                    atomicAdd(dst + 3, acc.w);
                    if (lane == 0) atomicAdd(&g_E[curg], acce);
                    acc = make_float4(0.f, 0.f, 0.f, 0.f);
                    acce = 0.f;
                    curg = g;
                }
                int rr = min(rowbase + r, n - 1);
                float4 xv = __ldg((const float4*)(x + (size_t)rr * NF) + lane);
                acc.x = fmaf(xv.x, e, acc.x);
                acc.y = fmaf(xv.y, e, acc.y);
                acc.z = fmaf(xv.z, e, acc.z);
                acc.w = fmaf(xv.w, e, acc.w);
                acce += e;
            }
            float* dst = pooled + (size_t)curg * NF + lane * 4;
            atomicAdd(dst + 0, acc.x);
            atomicAdd(dst + 1, acc.y);
            atomicAdd(dst + 2, acc.z);
            atomicAdd(dst + 3, acc.w);
            if (lane == 0) atomicAdd(&g_E[curg], acce);
        }
    }
}

// ---------------------------------------------------------------------------
// k_final: pooled[i] /= E ; attn[j] /= E[batch[j]]
// ---------------------------------------------------------------------------
__global__ void k_final(const int* __restrict__ batch, float* __restrict__ attn,
                        float* __restrict__ pooled, int n) {
    int i = blockIdx.x * 256 + threadIdx.x;
    const int total = NGRAPHS * NF;
    if (i < total) {
        float E = g_E[i >> 7];
        pooled[i] = (E > 0.f) ? pooled[i] / E : 0.f;
    } else {
        int j = i - total;
        if (j < n) attn[j] /= g_E[__ldg(batch + j)];
    }
}

// ---------------------------------------------------------------------------
extern "C" void kernel_launch(void* const* d_in, const int* in_sizes, int n_in,
                              void* d_out, int out_size) {
    const float* x     = (const float*)d_in[0];
    const float* u     = (const float*)d_in[1];
    const int*   batch = (const int*)  d_in[2];
    const float* W1    = (const float*)d_in[3];
    const float* b1    = (const float*)d_in[4];
    const float* W2    = (const float*)d_in[5];
    const float* b2    = (const float*)d_in[6];

    float* pooled = (float*)d_out;                     // [16384, 128]
    float* attn   = (float*)d_out + NGRAPHS * NF;      // [1e6]

    int n = in_sizes[2];
    int ntiles = (n + 127) / 128;

    k_init<<<296, 256>>>(u, W1, b1, pooled);
    k_mlp_fused<<<592, 128>>>(x, W1, W2, b2, batch, pooled, attn, n, ntiles);
    k_final<<<(NGRAPHS * NF + n + 255) / 256, 256>>>(batch, attn, pooled, n);
}